// round 7
// baseline (speedup 1.0000x reference)
#include <cuda_runtime.h>
#include <cuda_fp16.h>
#include <cstdint>

#define BB 16
#define NN 2048
#define DD 768
#define ROWS (BB*NN)

#define KCB 64                 // k bytes (int8 elems) per chunk
#define NCH (DD/KCB)           // 12 chunks per tile item
#define NITEMS (BB*16*16)      // 4096 (b, mt, nt) 128x128 tiles
#define GRID 296               // 148 SMs x 2 CTA/SM (persistent)
#define NSTAGE 6
#define SUB 8192               // one 128x64B sub-buffer (swizzled)
#define STAGE (2*SUB)          // A, B
#define SMEM_DYN (NSTAGE*STAGE + 128*8 + 128*4 + 128*4)   // 100352
#define CAP 64
#define MARGIN 8e-3f

// ---- scratch (allocation-free rule: __device__ globals) --------------------
__device__ __align__(16) int8_t g_Qb[(size_t)ROWS*DD];  // int8 quantized q-hat
__device__ __align__(16) int8_t g_Cb[(size_t)ROWS*DD];  // int8 quantized c-hat
__device__ float g_invq[ROWS];
__device__ float g_invc[ROWS];
__device__ float g_dc[ROWS];     // descale for cached rows
__device__ float g_qmarg[ROWS];  // MARGIN / d_q per query row
__device__ unsigned long long g_gmax[ROWS];
__device__ int   g_cnt[ROWS];
__device__ int   g_cand[(size_t)ROWS*CAP];

// ---------------------------------------------------------------------------
__device__ __forceinline__ uint32_t smem_u32(const void* p) {
    uint32_t a;
    asm("{ .reg .u64 t; cvta.to.shared.u64 t, %1; cvt.u32.u64 %0, t; }" : "=r"(a) : "l"(p));
    return a;
}
// swizzled offset inside one 128-row x 64B sub-buffer (conflict-free LDSM+STS)
__device__ __forceinline__ uint32_t swoff(int row, int piece) {
    return (uint32_t)(((row >> 1) * 128) +
                      ((((((row & 1) << 2) | piece)) ^ ((row >> 1) & 7)) << 4));
}
__device__ __forceinline__ unsigned long long packsc(float v, int col) {
    uint32_t b = __float_as_uint(v);
    uint32_t key = (b & 0x80000000u) ? ~b : (b | 0x80000000u);
    return ((unsigned long long)key << 32) | (uint32_t)(2047 - col);
}
__device__ __forceinline__ float unpack_score(unsigned long long p) {
    uint32_t key = (uint32_t)(p >> 32);
    uint32_t fb = (key & 0x80000000u) ? (key & 0x7FFFFFFFu) : ~key;
    return __uint_as_float(fb);
}

#define LDSM4(r, addr) \
    asm volatile("ldmatrix.sync.aligned.m8n8.x4.shared.b16 {%0,%1,%2,%3}, [%4];" \
        : "=r"((r)[0]), "=r"((r)[1]), "=r"((r)[2]), "=r"((r)[3]) : "r"(addr))

#define MMAS8(d, a, b) \
    asm volatile("mma.sync.aligned.m16n8k32.row.col.s32.s8.s8.s32 " \
        "{%0,%1,%2,%3}, {%4,%5,%6,%7}, {%8,%9}, {%0,%1,%2,%3};" \
        : "+r"((d)[0]), "+r"((d)[1]), "+r"((d)[2]), "+r"((d)[3]) \
        : "r"((a)[0]), "r"((a)[1]), "r"((a)[2]), "r"((a)[3]), "r"((b)[0]), "r"((b)[1]))

#define CP_ASYNC16(dst, src) \
    asm volatile("cp.async.cg.shared.global [%0], [%1], 16;" :: "r"(dst), "l"(src))
#define CP_COMMIT() asm volatile("cp.async.commit_group;" ::: "memory")
#define CP_WAIT4()  asm volatile("cp.async.wait_group 4;" ::: "memory")

// ---------------------------------------------------------------------------
// Prepass: per row: refined rsqrt norm; per-row amax of normalized row;
// symmetric int8 quantization; store invq/invc, descale (C) / margin (Q).
// grid (ROWS, 2): y==0 Q, y==1 C. 192 thr (4 elems/thread).
// ---------------------------------------------------------------------------
__global__ __launch_bounds__(192) void prep_kernel(const float* __restrict__ Qi,
                                                   const float* __restrict__ Ci) {
    const int r = blockIdx.x;
    const bool isC = (blockIdx.y != 0);
    __shared__ __align__(16) float row[DD];
    __shared__ float wsum[6], wmax[6];
    __shared__ float s_sc, s_qs;
    const int t = threadIdx.x;
    float4 v = ((const float4*)((isC ? Ci : Qi) + (size_t)r * DD))[t];
    ((float4*)row)[t] = v;
    float ss = v.x * v.x + v.y * v.y + v.z * v.z + v.w * v.w;
    float am = fmaxf(fmaxf(fabsf(v.x), fabsf(v.y)), fmaxf(fabsf(v.z), fabsf(v.w)));
#pragma unroll
    for (int o = 16; o > 0; o >>= 1) {
        ss += __shfl_xor_sync(~0u, ss, o);
        am = fmaxf(am, __shfl_xor_sync(~0u, am, o));
    }
    if ((t & 31) == 0) { wsum[t >> 5] = ss; wmax[t >> 5] = am; }
    __syncthreads();
    if (t == 0) {
        float s = wsum[0] + wsum[1] + wsum[2] + wsum[3] + wsum[4] + wsum[5];
        float m = fmaxf(fmaxf(fmaxf(wmax[0], wmax[1]), fmaxf(wmax[2], wmax[3])),
                        fmaxf(wmax[4], wmax[5]));
        float inv = rsqrtf(s);
        inv = inv * (1.5f - 0.5f * s * inv * inv);  // Newton -> ~fp32 exact
        float amax_hat = m * inv;                    // amax of normalized row
        float d = amax_hat * (1.f / 127.f);
        s_sc = inv * (127.f / amax_hat);             // quantization scale
        if (isC) { g_invc[r] = inv; g_dc[r] = d; }
        else {
            g_invq[r] = inv; g_qmarg[r] = MARGIN / d;
            g_cnt[r] = 0; g_gmax[r] = 0ull;
        }
    }
    __syncthreads();
    const float qs = s_sc;
    int8_t* dst = (isC ? g_Cb : g_Qb) + (size_t)r * DD;
    int i0 = __float2int_rn(row[4 * t + 0] * qs);
    int i1 = __float2int_rn(row[4 * t + 1] * qs);
    int i2 = __float2int_rn(row[4 * t + 2] * qs);
    int i3 = __float2int_rn(row[4 * t + 3] * qs);
    uint32_t u = (uint32_t)(i0 & 0xFF) | ((uint32_t)(i1 & 0xFF) << 8) |
                 ((uint32_t)(i2 & 0xFF) << 16) | ((uint32_t)(i3 & 0xFF) << 24);
    ((uint32_t*)dst)[t] = u;
}

// ---------------------------------------------------------------------------
// Persistent int8 approx GEMM + margin candidate collection.
// 296 CTAs, 256 thr, 2 CTA/SM. Items = 4096 (b, mt, nt) 128x128 tiles,
// strided: item = cta + k*GRID. 6-stage cp.async pipeline, K in 12 chunks
// of 64 int8. Epilogue per item: scaled tile max -> global running row max
// -> cut = globalmax - margin/d_q -> append candidate cols.
// ---------------------------------------------------------------------------
__global__ __launch_bounds__(256, 2) void gemm_kernel() {
    extern __shared__ __align__(1024) unsigned char smem[];
    const uint32_t sb = smem_u32(smem);
    unsigned long long* table = (unsigned long long*)(smem + NSTAGE * STAGE);
    float* tableF = (float*)(smem + NSTAGE * STAGE + 128 * 8);
    float* sDc    = (float*)(smem + NSTAGE * STAGE + 128 * 8 + 128 * 4);

    const int cta = blockIdx.x;
    const int tid = threadIdx.x, wid = tid >> 5, lane = tid & 31;
    const int wm = wid & 1, wn = wid >> 1;

    const int nit = (NITEMS - cta + GRID - 1) / GRID;
    const int nch_tot = nit * NCH;

    if (tid < 128) table[tid] = 0ull;
    __syncthreads();

    int acc[4][4][4];
#pragma unroll
    for (int i = 0; i < 4; i++)
#pragma unroll
        for (int j = 0; j < 4; j++)
#pragma unroll
            for (int c = 0; c < 4; c++) acc[i][j][c] = 0;

    auto issue_chunk = [&](int f, int stage_idx) {
        const int il = f / NCH, kc = f - il * NCH;
        const int item = cta + il * GRID;
        const int b = item >> 8, mt = (item >> 4) & 15, nt = item & 15;
        const uint32_t stage = sb + (uint32_t)stage_idx * STAGE;
        const int8_t* abase = g_Qb + (size_t)(b * NN + mt * 128) * DD + kc * KCB;
        const int8_t* bbase = g_Cb + (size_t)(b * NN + nt * 128) * DD + kc * KCB;
#pragma unroll
        for (int pp = 0; pp < 2; pp++) {
            const int p = tid * 2 + pp;
            const int row = p >> 2, q = p & 3;
            const uint32_t so = swoff(row, q);
            CP_ASYNC16(stage + so,       abase + (size_t)row * DD + q * 16);
            CP_ASYNC16(stage + SUB + so, bbase + (size_t)row * DD + q * 16);
        }
        CP_COMMIT();
    };

    // prologue: 5 chunks into stages 0..4
#pragma unroll
    for (int j = 0; j < 5; j++) issue_chunk(j, j);

    int cs = 0, is = 5;   // consume / issue stage (mod 6, rolling)
    for (int f = 0; f < nch_tot; f++) {
        CP_WAIT4();
        __syncthreads();
        const uint32_t abase = sb + (uint32_t)cs * STAGE;
#pragma unroll
        for (int kk = 0; kk < 2; kk++) {       // two k32 sub-steps per chunk
            uint32_t ah[4][4], bh[4][2];
            const int lr = lane & 15, lp = lane >> 4;
#pragma unroll
            for (int i = 0; i < 4; i++)
                LDSM4(ah[i], abase + swoff(wm * 64 + i * 16 + lr, kk * 2 + lp));
#pragma unroll
            for (int jp = 0; jp < 2; jp++) {
                const int nrow = wn * 32 + (jp * 2 + (lane >> 4)) * 8 + (lane & 7);
                const int piece = kk * 2 + ((lane >> 3) & 1);
                uint32_t r4[4];
                LDSM4(r4, abase + SUB + swoff(nrow, piece));
                bh[jp*2][0]=r4[0]; bh[jp*2][1]=r4[1]; bh[jp*2+1][0]=r4[2]; bh[jp*2+1][1]=r4[3];
            }
#pragma unroll
            for (int i = 0; i < 4; i++)
#pragma unroll
                for (int j = 0; j < 4; j++)
                    MMAS8(acc[i][j], ah[i], bh[j]);
        }
        if (f + 5 < nch_tot) { issue_chunk(f + 5, is); is = (is == 5) ? 0 : is + 1; }
        cs = (cs == 5) ? 0 : cs + 1;

        const int il = f / NCH;
        if (f - il * NCH == NCH - 1) {
            const int item = cta + il * GRID;
            const int b = item >> 8, mt = (item >> 4) & 15, nt = item & 15;
            const int qrow0 = b * NN + mt * 128;
            const int crow0 = b * NN + nt * 128;
            const int loccol = wn * 32 + (lane & 3) * 2;
            const int colbase = nt * 128 + loccol;
            // load per-col descale factors
            if (tid < 128) sDc[tid] = g_dc[crow0 + tid];
            __syncthreads();
            // phase 1: per-row tile max (descaled) into smem table
#pragma unroll
            for (int i = 0; i < 4; i++)
#pragma unroll
                for (int half = 0; half < 2; half++) {
                    float bv = -3.0e38f; int bc = 0;
#pragma unroll
                    for (int j = 0; j < 4; j++) {
                        const int lc = loccol + j * 8;
                        float v0 = (float)acc[i][j][half * 2 + 0] * sDc[lc];
                        if (v0 > bv) { bv = v0; bc = colbase + j * 8; }
                        float v1 = (float)acc[i][j][half * 2 + 1] * sDc[lc + 1];
                        if (v1 > bv) { bv = v1; bc = colbase + j * 8 + 1; }
                    }
#pragma unroll
                    for (int off = 1; off < 4; off <<= 1) {
                        float ov = __shfl_xor_sync(~0u, bv, off);
                        int   oc = __shfl_xor_sync(~0u, bc, off);
                        if (ov > bv || (ov == bv && oc < bc)) { bv = ov; bc = oc; }
                    }
                    if ((lane & 3) == 0) {
                        const int rloc = wm * 64 + i * 16 + half * 8 + (lane >> 2);
                        atomicMax(&table[rloc], packsc(bv, bc));
                    }
                }
            __syncthreads();
            // merge with global running row max -> cut (score/d_q units)
            if (tid < 128) {
                unsigned long long loc = table[tid];
                unsigned long long old = atomicMax(&g_gmax[qrow0 + tid], loc);
                if (old > loc) loc = old;
                tableF[tid] = unpack_score(loc) - g_qmarg[qrow0 + tid];
            }
            __syncthreads();
            // phase 2: append candidates >= cut
#pragma unroll
            for (int i = 0; i < 4; i++)
#pragma unroll
                for (int half = 0; half < 2; half++) {
                    const int rloc = wm * 64 + i * 16 + half * 8 + (lane >> 2);
                    const float cut = tableF[rloc];
                    const int rg = qrow0 + rloc;
#pragma unroll
                    for (int j = 0; j < 4; j++)
#pragma unroll
                        for (int c = 0; c < 2; c++) {
                            const int lc = loccol + j * 8 + c;
                            float v = (float)acc[i][j][half * 2 + c] * sDc[lc];
                            if (v >= cut) {
                                int slot = atomicAdd(&g_cnt[rg], 1);
                                if (slot < CAP)
                                    g_cand[(size_t)rg * CAP + slot] = colbase + j * 8 + c;
                            }
                        }
                }
            __syncthreads();
            if (tid < 128) table[tid] = 0ull;
            // next table use is >= 12 chunks away, separated by syncs.
#pragma unroll
            for (int i = 0; i < 4; i++)
#pragma unroll
                for (int j = 0; j < 4; j++)
#pragma unroll
                    for (int c = 0; c < 4; c++) acc[i][j][c] = 0;
        }
    }
}

// ---------------------------------------------------------------------------
// Fused exact rescore + blend. One block (192 thr) per row.
// out layout: [reuse_map (B*N)] [reuse_input (B*N*D)] [reuse_value (B*N*D)]
// ---------------------------------------------------------------------------
__global__ __launch_bounds__(192) void rescore_blend_kernel(
    const float* __restrict__ Qi, const float* __restrict__ Qv,
    const float* __restrict__ Ci, const float* __restrict__ Cv,
    const float* __restrict__ thr_raw, float* __restrict__ out) {
    const int r = blockIdx.x;
    const int b = r >> 11;
    const int n = r & (NN - 1);
    const int t = threadIdx.x, wid = t >> 5, lane = t & 31;

    __shared__ __align__(16) float q[DD];
    __shared__ unsigned long long wbest[6];
    __shared__ float s_rm;
    __shared__ int s_idx;

    ((float4*)q)[t] = ((const float4*)(Qi + (size_t)r * DD))[t];
    __syncthreads();

    int cnt = g_cnt[r]; if (cnt > CAP) cnt = CAP;
    const float invq = g_invq[r];
    unsigned long long best = 0ull;
    for (int ci = wid; ci < cnt; ci += 6) {
        const int idx = g_cand[(size_t)r * CAP + ci];
        const float4* crow = (const float4*)(Ci + ((size_t)(b * NN + idx)) * DD);
        float s = 0.f;
#pragma unroll
        for (int u = 0; u < 6; u++) {
            float4 cv = crow[lane + 32 * u];
            float4 qv = ((const float4*)q)[lane + 32 * u];
            s += cv.x * qv.x + cv.y * qv.y + cv.z * qv.z + cv.w * qv.w;
        }
#pragma unroll
        for (int o = 16; o > 0; o >>= 1) s += __shfl_xor_sync(~0u, s, o);
        if (lane == 0) {
            unsigned long long p = packsc(s * invq * g_invc[b * NN + idx], idx);
            if (p > best) best = p;
        }
    }
    if (lane == 0) wbest[wid] = best;
    __syncthreads();
    if (t == 0) {
        unsigned long long B = 0ull;
#pragma unroll
        for (int w = 0; w < 6; w++) if (wbest[w] > B) B = wbest[w];
        const float score = unpack_score(B);
        const int idx = 2047 - (int)(uint32_t)(B & 0xFFFFFFFFull);
        const float thr = 1.f / (1.f + expf(-thr_raw[n]));
        const float rm  = 1.f / (1.f + expf(-40.f * (score - thr)));
        s_rm = rm; s_idx = idx;
        out[r] = rm;
    }
    __syncthreads();
    const float rm = s_rm, om = 1.f - rm;
    const int idx = s_idx;
    const float4* qv = (const float4*)(Qv + (size_t)r * DD);
    const float4* ci = (const float4*)(Ci + ((size_t)b * NN + idx) * DD);
    const float4* cv = (const float4*)(Cv + ((size_t)b * NN + idx) * DD);
    float4* oi = (float4*)(out + ROWS + (size_t)r * DD);
    float4* ov = (float4*)(out + ROWS + (size_t)ROWS * DD + (size_t)r * DD);

    float4 a = ((const float4*)q)[t], c = ci[t];
    oi[t] = make_float4(om * a.x + rm * c.x, om * a.y + rm * c.y,
                        om * a.z + rm * c.z, om * a.w + rm * c.w);
    float4 av = qv[t], cvv = cv[t];
    ov[t] = make_float4(om * av.x + rm * cvv.x, om * av.y + rm * cvv.y,
                        om * av.z + rm * cvv.z, om * av.w + rm * cvv.w);
}

// ---------------------------------------------------------------------------
extern "C" void kernel_launch(void* const* d_in, const int* in_sizes, int n_in,
                              void* d_out, int out_size) {
    const float* Qi = (const float*)d_in[0];
    const float* Qv = (const float*)d_in[1];
    const float* Ci = (const float*)d_in[2];
    const float* Cv = (const float*)d_in[3];
    const float* Th = (const float*)d_in[4];
    float* out = (float*)d_out;

    cudaFuncSetAttribute(gemm_kernel,
                         cudaFuncAttributeMaxDynamicSharedMemorySize, SMEM_DYN);

    prep_kernel<<<dim3(ROWS, 2), 192>>>(Qi, Ci);
    gemm_kernel<<<GRID, 256, SMEM_DYN>>>();
    rescore_blend_kernel<<<ROWS, 192>>>(Qi, Qv, Ci, Cv, Th, out);
}

// round 8
// speedup vs baseline: 1.7225x; 1.7225x over previous
#include <cuda_runtime.h>
#include <cuda_fp16.h>
#include <cstdint>

#define BB 16
#define NN 2048
#define DD 768
#define ROWS (BB*NN)

#define KC 32                  // k elems per chunk
#define NCH (DD/KC)            // 24 chunks per tile item
#define NITEMS (BB*16*8)       // 2048 (b, mt, nt) 128x256 tiles
#define GRID 296               // 148 SMs x 2 CTA/SM (persistent)
#define NSTAGE 4
#define SUB_A 8192             // 128 rows x 64B (swizzled)
#define SUB_B 16384            // 256 rows x 64B (swizzled)
#define STAGE (SUB_A+SUB_B)    // 24576
#define SMEM_DYN (NSTAGE*STAGE + 128*8 + 128*4)   // 99840
#define CAP 64
#define MARGIN 2e-3f

// ---- scratch (allocation-free rule: __device__ globals) --------------------
__device__ __align__(16) __half g_Qh[(size_t)ROWS*DD];  // fp16(q/||q||)
__device__ __align__(16) __half g_Ch[(size_t)ROWS*DD];  // fp16(c/||c||)
__device__ float g_invq[ROWS];
__device__ float g_invc[ROWS];
__device__ unsigned long long g_gmax[ROWS];
__device__ int   g_cnt[ROWS];
__device__ int   g_cand[(size_t)ROWS*CAP];

// ---------------------------------------------------------------------------
__device__ __forceinline__ uint32_t smem_u32(const void* p) {
    uint32_t a;
    asm("{ .reg .u64 t; cvta.to.shared.u64 t, %1; cvt.u32.u64 %0, t; }" : "=r"(a) : "l"(p));
    return a;
}
// swizzled offset inside one N-row x 64B sub-buffer (conflict-free LDSM+STS)
__device__ __forceinline__ uint32_t swoff(int row, int piece) {
    return (uint32_t)(((row >> 1) * 128) +
                      ((((((row & 1) << 2) | piece)) ^ ((row >> 1) & 7)) << 4));
}
__device__ __forceinline__ unsigned long long packsc(float v, int col) {
    uint32_t b = __float_as_uint(v);
    uint32_t key = (b & 0x80000000u) ? ~b : (b | 0x80000000u);
    return ((unsigned long long)key << 32) | (uint32_t)(2047 - col);
}
__device__ __forceinline__ float unpack_score(unsigned long long p) {
    uint32_t key = (uint32_t)(p >> 32);
    uint32_t fb = (key & 0x80000000u) ? (key & 0x7FFFFFFFu) : ~key;
    return __uint_as_float(fb);
}

#define LDSM4(r, addr) \
    asm volatile("ldmatrix.sync.aligned.m8n8.x4.shared.b16 {%0,%1,%2,%3}, [%4];" \
        : "=r"((r)[0]), "=r"((r)[1]), "=r"((r)[2]), "=r"((r)[3]) : "r"(addr))

// fp16-accumulate HMMA: d(2x half2) = a(4) x b(2) + d
#define MMAH(d, a, b) \
    asm volatile("mma.sync.aligned.m16n8k16.row.col.f16.f16.f16.f16 " \
        "{%0,%1}, {%2,%3,%4,%5}, {%6,%7}, {%0,%1};" \
        : "+r"((d)[0]), "+r"((d)[1]) \
        : "r"((a)[0]), "r"((a)[1]), "r"((a)[2]), "r"((a)[3]), "r"((b)[0]), "r"((b)[1]))

#define CP_ASYNC16(dst, src) \
    asm volatile("cp.async.cg.shared.global [%0], [%1], 16;" :: "r"(dst), "l"(src))
#define CP_COMMIT() asm volatile("cp.async.commit_group;" ::: "memory")
#define CP_WAIT2()  asm volatile("cp.async.wait_group 2;" ::: "memory")

// ---------------------------------------------------------------------------
// Prepass: per row: refined rsqrt norm; write fp16(normalized row); store
// invq / invc; zero g_gmax / g_cnt. grid (ROWS, 2): y==0 Q, y==1 C. 192 thr.
// ---------------------------------------------------------------------------
__global__ __launch_bounds__(192) void prep_kernel(const float* __restrict__ Qi,
                                                   const float* __restrict__ Ci) {
    const int r = blockIdx.x;
    const bool isC = (blockIdx.y != 0);
    __shared__ __align__(16) float row[DD];
    __shared__ float wsum[6];
    __shared__ float s_sc;
    const int t = threadIdx.x;
    float4 v = ((const float4*)((isC ? Ci : Qi) + (size_t)r * DD))[t];
    ((float4*)row)[t] = v;
    float ss = v.x * v.x + v.y * v.y + v.z * v.z + v.w * v.w;
#pragma unroll
    for (int o = 16; o > 0; o >>= 1) ss += __shfl_xor_sync(~0u, ss, o);
    if ((t & 31) == 0) wsum[t >> 5] = ss;
    __syncthreads();
    if (t == 0) {
        float s = wsum[0] + wsum[1] + wsum[2] + wsum[3] + wsum[4] + wsum[5];
        float inv = rsqrtf(s);
        inv = inv * (1.5f - 0.5f * s * inv * inv);  // Newton -> ~fp32 exact
        s_sc = inv;
        if (isC) g_invc[r] = inv;
        else { g_invq[r] = inv; g_cnt[r] = 0; g_gmax[r] = 0ull; }
    }
    __syncthreads();
    const float sc = s_sc;
    __half* dst = (isC ? g_Ch : g_Qh) + (size_t)r * DD;
    __half2 h0 = __floats2half2_rn(row[4 * t + 0] * sc, row[4 * t + 1] * sc);
    __half2 h1 = __floats2half2_rn(row[4 * t + 2] * sc, row[4 * t + 3] * sc);
    uint2 u;
    u.x = *(uint32_t*)&h0; u.y = *(uint32_t*)&h1;
    ((uint2*)dst)[t] = u;
}

// ---------------------------------------------------------------------------
// Persistent fp16 (fp16-accum) approx GEMM + margin candidate collection.
// 296 CTAs, 256 thr, 2 CTA/SM. Items = 2048 (b, mt, nt) 128x256 tiles,
// strided: item = cta + k*GRID. Warp tile 64x64 (8 warps = 2m x 4n).
// 4-stage cp.async pipeline, K in 24 chunks of 32.
// ---------------------------------------------------------------------------
__global__ __launch_bounds__(256, 2) void gemm_kernel() {
    extern __shared__ __align__(1024) unsigned char smem[];
    const uint32_t sb = smem_u32(smem);
    unsigned long long* table = (unsigned long long*)(smem + NSTAGE * STAGE);
    float* tableF = (float*)(smem + NSTAGE * STAGE + 128 * 8);

    const int cta = blockIdx.x;
    const int tid = threadIdx.x, wid = tid >> 5, lane = tid & 31;
    const int wm = wid & 1, wn = wid >> 1;

    const int nit = (NITEMS - cta + GRID - 1) / GRID;
    const int nch_tot = nit * NCH;

    if (tid < 128) table[tid] = 0ull;
    __syncthreads();

    uint32_t acc[4][8][2];   // fp16x2 accumulators: 64x64 warp tile
#pragma unroll
    for (int i = 0; i < 4; i++)
#pragma unroll
        for (int j = 0; j < 8; j++) { acc[i][j][0] = 0u; acc[i][j][1] = 0u; }

    auto issue_chunk = [&](int f, int stage_idx) {
        const int il = f / NCH, kc = f - il * NCH;
        const int item = cta + il * GRID;
        const int b = item >> 7, mt = (item >> 3) & 15, nt = item & 7;
        const uint32_t stage = sb + (uint32_t)stage_idx * STAGE;
        const __half* abase = g_Qh + (size_t)(b * NN + mt * 128) * DD + kc * KC;
        const __half* bbase = g_Ch + (size_t)(b * NN + nt * 256) * DD + kc * KC;
        // A: 128 rows x 4 pieces = 512 x 16B, 2 per thread
#pragma unroll
        for (int pp = 0; pp < 2; pp++) {
            const int p = tid * 2 + pp;
            const int row = p >> 2, q = p & 3;
            CP_ASYNC16(stage + swoff(row, q), abase + (size_t)row * DD + q * 8);
        }
        // B: 256 rows x 4 pieces = 1024 x 16B, 4 per thread
#pragma unroll
        for (int pp = 0; pp < 4; pp++) {
            const int p = tid * 4 + pp;
            const int row = p >> 2, q = p & 3;
            CP_ASYNC16(stage + SUB_A + swoff(row, q), bbase + (size_t)row * DD + q * 8);
        }
        CP_COMMIT();
    };

    // prologue: 3 chunks into stages 0..2
#pragma unroll
    for (int j = 0; j < 3; j++) issue_chunk(j, j);

    int cs = 0, is = 3;   // consume / issue stage (mod 4, rolling)
    for (int f = 0; f < nch_tot; f++) {
        CP_WAIT2();
        __syncthreads();
        const uint32_t abase = sb + (uint32_t)cs * STAGE;
#pragma unroll
        for (int kk = 0; kk < 2; kk++) {       // two k16 sub-steps per chunk
            uint32_t ah[4][4];
            const int lr = lane & 15, lp = lane >> 4;
#pragma unroll
            for (int i = 0; i < 4; i++)
                LDSM4(ah[i], abase + swoff(wm * 64 + i * 16 + lr, kk * 2 + lp));
#pragma unroll
            for (int jp = 0; jp < 4; jp++) {
                const int nrow = wn * 64 + (jp * 2 + (lane >> 4)) * 8 + (lane & 7);
                const int piece = kk * 2 + ((lane >> 3) & 1);
                uint32_t r4[4];
                LDSM4(r4, abase + SUB_A + swoff(nrow, piece));
                uint32_t b0[2] = { r4[0], r4[1] };
                uint32_t b1[2] = { r4[2], r4[3] };
#pragma unroll
                for (int i = 0; i < 4; i++) {
                    MMAH(acc[i][jp * 2 + 0], ah[i], b0);
                    MMAH(acc[i][jp * 2 + 1], ah[i], b1);
                }
            }
        }
        if (f + 3 < nch_tot) { issue_chunk(f + 3, is); is = (is + 1) & 3; }
        cs = (cs + 1) & 3;

        const int il = f / NCH;
        if (f - il * NCH == NCH - 1) {
            const int item = cta + il * GRID;
            const int b = item >> 7, mt = (item >> 3) & 15, nt = item & 7;
            const int qrow0 = b * NN + mt * 128;
            const int colbase = nt * 256 + wn * 64 + (lane & 3) * 2;
            // phase 1: per-row tile max into smem table
#pragma unroll
            for (int i = 0; i < 4; i++)
#pragma unroll
                for (int half = 0; half < 2; half++) {
                    float bv = -3.0e38f; int bc = 0;
#pragma unroll
                    for (int j = 0; j < 8; j++) {
                        float2 fv = __half22float2(
                            *reinterpret_cast<const __half2*>(&acc[i][j][half]));
                        const int c0 = colbase + j * 8;
                        if (fv.x > bv) { bv = fv.x; bc = c0; }
                        if (fv.y > bv) { bv = fv.y; bc = c0 + 1; }
                    }
#pragma unroll
                    for (int off = 1; off < 4; off <<= 1) {
                        float ov = __shfl_xor_sync(~0u, bv, off);
                        int   oc = __shfl_xor_sync(~0u, bc, off);
                        if (ov > bv || (ov == bv && oc < bc)) { bv = ov; bc = oc; }
                    }
                    if ((lane & 3) == 0) {
                        const int rloc = wm * 64 + i * 16 + half * 8 + (lane >> 2);
                        atomicMax(&table[rloc], packsc(bv, bc));
                    }
                }
            __syncthreads();
            // merge with global running row max -> cut
            if (tid < 128) {
                unsigned long long loc = table[tid];
                unsigned long long old = atomicMax(&g_gmax[qrow0 + tid], loc);
                if (old > loc) loc = old;
                tableF[tid] = unpack_score(loc) - MARGIN;
            }
            __syncthreads();
            // phase 2: append candidates >= cut
#pragma unroll
            for (int i = 0; i < 4; i++)
#pragma unroll
                for (int half = 0; half < 2; half++) {
                    const int rloc = wm * 64 + i * 16 + half * 8 + (lane >> 2);
                    const float cut = tableF[rloc];
                    const int rg = qrow0 + rloc;
#pragma unroll
                    for (int j = 0; j < 8; j++) {
                        float2 fv = __half22float2(
                            *reinterpret_cast<const __half2*>(&acc[i][j][half]));
                        if (fv.x >= cut) {
                            int slot = atomicAdd(&g_cnt[rg], 1);
                            if (slot < CAP)
                                g_cand[(size_t)rg * CAP + slot] = colbase + j * 8;
                        }
                        if (fv.y >= cut) {
                            int slot = atomicAdd(&g_cnt[rg], 1);
                            if (slot < CAP)
                                g_cand[(size_t)rg * CAP + slot] = colbase + j * 8 + 1;
                        }
                    }
                }
            __syncthreads();
            if (tid < 128) table[tid] = 0ull;
            // next table use is >= 24 chunks away, separated by syncs.
#pragma unroll
            for (int i = 0; i < 4; i++)
#pragma unroll
                for (int j = 0; j < 8; j++) { acc[i][j][0] = 0u; acc[i][j][1] = 0u; }
        }
    }
}

// ---------------------------------------------------------------------------
// Fused exact rescore + blend. One block (192 thr) per row.
// out layout: [reuse_map (B*N)] [reuse_input (B*N*D)] [reuse_value (B*N*D)]
// ---------------------------------------------------------------------------
__global__ __launch_bounds__(192) void rescore_blend_kernel(
    const float* __restrict__ Qi, const float* __restrict__ Qv,
    const float* __restrict__ Ci, const float* __restrict__ Cv,
    const float* __restrict__ thr_raw, float* __restrict__ out) {
    const int r = blockIdx.x;
    const int b = r >> 11;
    const int n = r & (NN - 1);
    const int t = threadIdx.x, wid = t >> 5, lane = t & 31;

    __shared__ __align__(16) float q[DD];
    __shared__ unsigned long long wbest[6];
    __shared__ float s_rm;
    __shared__ int s_idx;

    ((float4*)q)[t] = ((const float4*)(Qi + (size_t)r * DD))[t];
    __syncthreads();

    int cnt = g_cnt[r]; if (cnt > CAP) cnt = CAP;
    const float invq = g_invq[r];
    unsigned long long best = 0ull;
    for (int ci = wid; ci < cnt; ci += 6) {
        const int idx = g_cand[(size_t)r * CAP + ci];
        const float4* crow = (const float4*)(Ci + ((size_t)(b * NN + idx)) * DD);
        float s = 0.f;
#pragma unroll
        for (int u = 0; u < 6; u++) {
            float4 cv = crow[lane + 32 * u];
            float4 qv = ((const float4*)q)[lane + 32 * u];
            s += cv.x * qv.x + cv.y * qv.y + cv.z * qv.z + cv.w * qv.w;
        }
#pragma unroll
        for (int o = 16; o > 0; o >>= 1) s += __shfl_xor_sync(~0u, s, o);
        if (lane == 0) {
            unsigned long long p = packsc(s * invq * g_invc[b * NN + idx], idx);
            if (p > best) best = p;
        }
    }
    if (lane == 0) wbest[wid] = best;
    __syncthreads();
    if (t == 0) {
        unsigned long long B = 0ull;
#pragma unroll
        for (int w = 0; w < 6; w++) if (wbest[w] > B) B = wbest[w];
        const float score = unpack_score(B);
        const int idx = 2047 - (int)(uint32_t)(B & 0xFFFFFFFFull);
        const float thr = 1.f / (1.f + expf(-thr_raw[n]));
        const float rm  = 1.f / (1.f + expf(-40.f * (score - thr)));
        s_rm = rm; s_idx = idx;
        out[r] = rm;
    }
    __syncthreads();
    const float rm = s_rm, om = 1.f - rm;
    const int idx = s_idx;
    const float4* qv = (const float4*)(Qv + (size_t)r * DD);
    const float4* ci = (const float4*)(Ci + ((size_t)b * NN + idx) * DD);
    const float4* cv = (const float4*)(Cv + ((size_t)b * NN + idx) * DD);
    float4* oi = (float4*)(out + ROWS + (size_t)r * DD);
    float4* ov = (float4*)(out + ROWS + (size_t)ROWS * DD + (size_t)r * DD);

    float4 a = ((const float4*)q)[t], c = ci[t];
    oi[t] = make_float4(om * a.x + rm * c.x, om * a.y + rm * c.y,
                        om * a.z + rm * c.z, om * a.w + rm * c.w);
    float4 av = qv[t], cvv = cv[t];
    ov[t] = make_float4(om * av.x + rm * cvv.x, om * av.y + rm * cvv.y,
                        om * av.z + rm * cvv.z, om * av.w + rm * cvv.w);
}

// ---------------------------------------------------------------------------
extern "C" void kernel_launch(void* const* d_in, const int* in_sizes, int n_in,
                              void* d_out, int out_size) {
    const float* Qi = (const float*)d_in[0];
    const float* Qv = (const float*)d_in[1];
    const float* Ci = (const float*)d_in[2];
    const float* Cv = (const float*)d_in[3];
    const float* Th = (const float*)d_in[4];
    float* out = (float*)d_out;

    cudaFuncSetAttribute(gemm_kernel,
                         cudaFuncAttributeMaxDynamicSharedMemorySize, SMEM_DYN);

    prep_kernel<<<dim3(ROWS, 2), 192>>>(Qi, Ci);
    gemm_kernel<<<GRID, 256, SMEM_DYN>>>();
    rescore_blend_kernel<<<ROWS, 192>>>(Qi, Qv, Ci, Cv, Th, out);
}